// round 16
// baseline (speedup 1.0000x reference)
#include <cuda_runtime.h>
#include <cuda_fp16.h>
#include <cuda_bf16.h>
#include <cstdint>

#define N_NODES 100000
#define N_EDGES 3200000
#define D_IN    256
#define D_HID   256
#define D_OUT   128

// ---------------- scratch (static device globals; no allocation) ----------------
__device__ __half g_h1  [(size_t)N_NODES * D_HID];   // dinv[m] * (X @ W1)   (half, pre-scaled)
__device__ __half g_agg1[(size_t)N_NODES * D_HID];   // relu(agg + b1)       (half)
__device__ __half g_h2  [(size_t)N_NODES * D_OUT];   // dinv[m] * (agg1 @ W2)(half, pre-scaled)
__device__ int    g_esrc[N_EDGES];                   // CSR: src per edge (dst-sorted)
__device__ int    g_rowptr[N_NODES + 1];
__device__ int    g_cursor[N_NODES];
__device__ int    g_cnt   [N_NODES];                 // incoming-edge count (no self loop)
__device__ float  g_dinv  [N_NODES];

// ---------------- prep ----------------
__global__ void k_zero_cnt(int n) {
    int i = blockIdx.x * blockDim.x + threadIdx.x;
    if (i < n) g_cnt[i] = 0;
}

// edge_index is int32 (JAX x64 disabled). 4 edges per thread.
__global__ void k_count(const int* __restrict__ ei, int nE) {
    int t = blockIdx.x * blockDim.x + threadIdx.x;
    if (t * 4 >= nE) return;
    int4 d = ((const int4*)(ei + nE))[t];
    atomicAdd(&g_cnt[d.x], 1);
    atomicAdd(&g_cnt[d.y], 1);
    atomicAdd(&g_cnt[d.z], 1);
    atomicAdd(&g_cnt[d.w], 1);
}

// single-block exclusive scan over g_cnt -> g_rowptr, init g_cursor, compute dinv
__global__ void k_scan(int n) {
    const int T = 1024;
    __shared__ int s[T];
    int t = threadIdx.x;
    int items = (n + T - 1) / T;
    int base = t * items;

    int sum = 0;
    for (int j = 0; j < items; j++) {
        int idx = base + j;
        if (idx < n) sum += g_cnt[idx];
    }
    s[t] = sum;
    __syncthreads();
    for (int off = 1; off < T; off <<= 1) {
        int v = (t >= off) ? s[t - off] : 0;
        __syncthreads();
        s[t] += v;
        __syncthreads();
    }
    int run = s[t] - sum;   // exclusive prefix
    for (int j = 0; j < items; j++) {
        int idx = base + j;
        if (idx < n) {
            int c = g_cnt[idx];
            g_rowptr[idx] = run;
            g_cursor[idx] = run;
            run += c;
            g_dinv[idx] = rsqrtf((float)(c + 1));   // +1 self loop
        }
    }
    if (t == T - 1) g_rowptr[n] = s[T - 1];
}

// 4 edges per thread: int4 src/dst loads, 4 independent cursor atomics,
// 4 independent int scatter stores (src only — norm factorized away).
__global__ void k_fill(const int* __restrict__ ei, int nE) {
    int t = blockIdx.x * blockDim.x + threadIdx.x;
    if (t * 4 >= nE) return;
    int4 s = ((const int4*)ei)[t];
    int4 d = ((const int4*)(ei + nE))[t];
    int p0 = atomicAdd(&g_cursor[d.x], 1);
    int p1 = atomicAdd(&g_cursor[d.y], 1);
    int p2 = atomicAdd(&g_cursor[d.z], 1);
    int p3 = atomicAdd(&g_cursor[d.w], 1);
    g_esrc[p0] = s.x;
    g_esrc[p1] = s.y;
    g_esrc[p2] = s.z;
    g_esrc[p3] = s.w;
}

// ---------------- BF16 tensor-core GEMM: H(half) = dinv[m] * (A @ W) --------
__device__ __forceinline__ uint32_t pack_bf2(float a, float b) {
    __nv_bfloat162 v = __floats2bfloat162_rn(a, b);
    return *(uint32_t*)&v;
}

template<int N, bool A_HALF>
__global__ __launch_bounds__(256, 2)
void gemm_bf16(const void* __restrict__ Av, const float* __restrict__ W,
               __half* __restrict__ H, int M)
{
    constexpr int K  = 256;
    constexpr int BK = 16;
    constexpr int NI = K / BK;                 // 16 slabs
    constexpr int ST = 136;                    // word stride (136 % 32 == 8)
    __shared__ uint32_t As[2][(BK / 2) * ST];
    __shared__ uint32_t Bs[2][(BK / 2) * ST];

    const int tid   = threadIdx.x;
    const int lane  = tid & 31;
    const int wid   = tid >> 5;
    const int warpM = wid & 1;
    const int warpN = wid >> 1;
    const int g     = lane >> 2;
    const int tig   = lane & 3;

    const int bm = blockIdx.y * 128;
    const int bn = blockIdx.x * 128;

    const int arow0 = tid >> 2;                // 0..63
    const int akq0  = (tid & 3) * 4;
    const int arow1 = (tid + 256) >> 2;        // 64..127
    const int hrow  = tid >> 1;                // 0..127
    const int hkq   = (tid & 1) * 8;           // 0 or 8

    float aReg[8];
    uint4 aRaw;
    float bReg[8];

    auto load_tile = [&](int k0) {
        if (A_HALF) {
            const __half* Ah = (const __half*)Av;
            aRaw = make_uint4(0, 0, 0, 0);
            if (bm + hrow < M)
                aRaw = *(const uint4*)(Ah + (size_t)(bm + hrow) * K + k0 + hkq);
        } else {
            const float* A = (const float*)Av;
            float4 a0 = make_float4(0.f, 0.f, 0.f, 0.f);
            float4 a1 = make_float4(0.f, 0.f, 0.f, 0.f);
            if (bm + arow0 < M) a0 = *(const float4*)(A + (size_t)(bm + arow0) * K + k0 + akq0);
            if (bm + arow1 < M) a1 = *(const float4*)(A + (size_t)(bm + arow1) * K + k0 + akq0);
            aReg[0] = a0.x; aReg[1] = a0.y; aReg[2] = a0.z; aReg[3] = a0.w;
            aReg[4] = a1.x; aReg[5] = a1.y; aReg[6] = a1.z; aReg[7] = a1.w;
        }
        #pragma unroll
        for (int it = 0; it < 4; it++) {
            int idx = tid + it * 256;
            int k2  = idx >> 7;
            int n   = idx & 127;
            bReg[it * 2]     = W[(size_t)(k0 + 2 * k2)     * N + bn + n];
            bReg[it * 2 + 1] = W[(size_t)(k0 + 2 * k2 + 1) * N + bn + n];
        }
    };
    auto store_tile = [&](int buf) {
        if (A_HALF) {
            const __half2* hp = (const __half2*)&aRaw;
            #pragma unroll
            for (int j = 0; j < 4; j++) {
                float2 f = __half22float2(hp[j]);
                As[buf][(hkq / 2 + j) * ST + hrow] = pack_bf2(f.x, f.y);
            }
        } else {
            As[buf][(akq0 / 2)     * ST + arow0] = pack_bf2(aReg[0], aReg[1]);
            As[buf][(akq0 / 2 + 1) * ST + arow0] = pack_bf2(aReg[2], aReg[3]);
            As[buf][(akq0 / 2)     * ST + arow1] = pack_bf2(aReg[4], aReg[5]);
            As[buf][(akq0 / 2 + 1) * ST + arow1] = pack_bf2(aReg[6], aReg[7]);
        }
        #pragma unroll
        for (int it = 0; it < 4; it++) {
            int idx = tid + it * 256;
            int k2  = idx >> 7;
            int n   = idx & 127;
            Bs[buf][k2 * ST + n] = pack_bf2(bReg[it * 2], bReg[it * 2 + 1]);
        }
    };

    float c[4][4][4];
    #pragma unroll
    for (int am = 0; am < 4; am++)
        #pragma unroll
        for (int an = 0; an < 4; an++)
            #pragma unroll
            for (int r = 0; r < 4; r++) c[am][an][r] = 0.f;

    load_tile(0);
    store_tile(0);
    __syncthreads();

    for (int it = 0; it < NI; it++) {
        int cur = it & 1;
        if (it + 1 < NI) load_tile((it + 1) * BK);

        uint32_t af[4][4];
        #pragma unroll
        for (int am = 0; am < 4; am++) {
            int m0 = warpM * 64 + am * 16 + g;
            af[am][0] = As[cur][tig       * ST + m0];
            af[am][1] = As[cur][tig       * ST + m0 + 8];
            af[am][2] = As[cur][(tig + 4) * ST + m0];
            af[am][3] = As[cur][(tig + 4) * ST + m0 + 8];
        }
        uint32_t bf[4][2];
        #pragma unroll
        for (int an = 0; an < 4; an++) {
            int n0 = warpN * 32 + an * 8 + g;
            bf[an][0] = Bs[cur][tig       * ST + n0];
            bf[an][1] = Bs[cur][(tig + 4) * ST + n0];
        }
        #pragma unroll
        for (int am = 0; am < 4; am++)
            #pragma unroll
            for (int an = 0; an < 4; an++) {
                asm volatile(
                    "mma.sync.aligned.m16n8k16.row.col.f32.bf16.bf16.f32 "
                    "{%0,%1,%2,%3}, {%4,%5,%6,%7}, {%8,%9}, {%0,%1,%2,%3};"
                    : "+f"(c[am][an][0]), "+f"(c[am][an][1]),
                      "+f"(c[am][an][2]), "+f"(c[am][an][3])
                    : "r"(af[am][0]), "r"(af[am][1]), "r"(af[am][2]), "r"(af[am][3]),
                      "r"(bf[an][0]), "r"(bf[an][1]));
            }

        if (it + 1 < NI) {
            store_tile(1 - cur);
            __syncthreads();
        }
    }

    // ---- epilogue: pre-scale rows by dinv, store half2 pairs ----
    #pragma unroll
    for (int am = 0; am < 4; am++) {
        int row = bm + warpM * 64 + am * 16 + g;
        float d0 = (row     < M) ? g_dinv[row]     : 0.f;
        float d1 = (row + 8 < M) ? g_dinv[row + 8] : 0.f;
        #pragma unroll
        for (int an = 0; an < 4; an++) {
            int col = bn + warpN * 32 + an * 8 + tig * 2;
            if (row < M)
                *(__half2*)(H + (size_t)row * N + col) =
                    __floats2half2_rn(c[am][an][0] * d0, c[am][an][1] * d0);
            if (row + 8 < M)
                *(__half2*)(H + (size_t)(row + 8) * N + col) =
                    __floats2half2_rn(c[am][an][2] * d1, c[am][an][3] * d1);
        }
    }
}

// ---------------- CSR aggregation: unweighted sum of pre-scaled rows ----------
// Index stream read as int4 after a scalar alignment prologue.
__device__ __forceinline__ void unpack4(uint2 r, float* f) {
    float2 a = __half22float2(*(const __half2*)&r.x);
    float2 b = __half22float2(*(const __half2*)&r.y);
    f[0] = a.x; f[1] = a.y; f[2] = b.x; f[3] = b.y;
}

template<int D, int ACT>
__global__ __launch_bounds__(256)
void k_agg_csr(const __half* __restrict__ h, const float* __restrict__ bias,
               void* __restrict__ outp)
{
    constexpr int L   = D / 4;      // lanes per node (64 or 32)
    constexpr int NPB = 256 / L;    // nodes per block (4 or 8)

    int grp  = threadIdx.x / L;
    int lane = threadIdx.x % L;
    int i = blockIdx.x * NPB + grp;
    if (i >= N_NODES) return;

    const uint2* hv = (const uint2*)h;      // row = L uint2s (4 halves each)
    int beg = g_rowptr[i];
    int end = g_rowptr[i + 1];

    float acc[4];
    {
        float f[4]; unpack4(__ldg(hv + (size_t)i * L + lane), f);
        #pragma unroll
        for (int j = 0; j < 4; j++) acc[j] = f[j];   // self loop (pre-scaled)
    }

    int e = beg;
    // scalar prologue to 4-edge alignment
    int alim = (beg + 3) & ~3;
    for (; e < end && e < alim; e++) {
        float f[4]; unpack4(__ldg(hv + (size_t)__ldg(g_esrc + e) * L + lane), f);
        #pragma unroll
        for (int j = 0; j < 4; j++) acc[j] += f[j];
    }
    // main loop: 8 edges per iteration, indices via 2x int4
    for (; e + 8 <= end; e += 8) {
        int4 i0 = __ldg((const int4*)(g_esrc + e));
        int4 i1 = __ldg((const int4*)(g_esrc + e + 4));
        uint2 r[8];
        r[0] = __ldg(hv + (size_t)i0.x * L + lane);
        r[1] = __ldg(hv + (size_t)i0.y * L + lane);
        r[2] = __ldg(hv + (size_t)i0.z * L + lane);
        r[3] = __ldg(hv + (size_t)i0.w * L + lane);
        r[4] = __ldg(hv + (size_t)i1.x * L + lane);
        r[5] = __ldg(hv + (size_t)i1.y * L + lane);
        r[6] = __ldg(hv + (size_t)i1.z * L + lane);
        r[7] = __ldg(hv + (size_t)i1.w * L + lane);
        #pragma unroll
        for (int u = 0; u < 8; u++) {
            float f[4]; unpack4(r[u], f);
            #pragma unroll
            for (int j = 0; j < 4; j++) acc[j] += f[j];
        }
    }
    // epilogue
    for (; e < end; e++) {
        float f[4]; unpack4(__ldg(hv + (size_t)__ldg(g_esrc + e) * L + lane), f);
        #pragma unroll
        for (int j = 0; j < 4; j++) acc[j] += f[j];
    }

    float dv = g_dinv[i];
    float4 b = __ldg((const float4*)bias + lane);
    acc[0] = acc[0] * dv + b.x;
    acc[1] = acc[1] * dv + b.y;
    acc[2] = acc[2] * dv + b.z;
    acc[3] = acc[3] * dv + b.w;
    if (ACT == 0) {
        #pragma unroll
        for (int j = 0; j < 4; j++) acc[j] = fmaxf(acc[j], 0.f);
        uint2 r;
        *(__half2*)&r.x = __floats2half2_rn(acc[0], acc[1]);
        *(__half2*)&r.y = __floats2half2_rn(acc[2], acc[3]);
        __stcs((uint2*)outp + (size_t)i * L + lane, r);
    } else {
        #pragma unroll
        for (int j = 0; j < 4; j++) acc[j] = 1.f / (1.f + __expf(-acc[j]));
        __stcs((float4*)((float*)outp + (size_t)i * D + lane * 4),
               make_float4(acc[0], acc[1], acc[2], acc[3]));
    }
}

// ---------------- launch ----------------
extern "C" void kernel_launch(void* const* d_in, const int* in_sizes, int n_in,
                              void* d_out, int out_size)
{
    const float* x  = (const float*)d_in[0];
    const int*   ei = (const int*)d_in[1];      // int32 edge_index [2, E]
    const float* W1 = (const float*)d_in[2];
    const float* b1 = (const float*)d_in[3];
    const float* W2 = (const float*)d_in[4];
    const float* b2 = (const float*)d_in[5];
    float*       out = (float*)d_out;

    const int M  = N_NODES;
    const int nE = N_EDGES;

    __half *h1, *h2, *agg1;
    cudaGetSymbolAddress((void**)&h1,   g_h1);
    cudaGetSymbolAddress((void**)&agg1, g_agg1);
    cudaGetSymbolAddress((void**)&h2,   g_h2);

    // CSR + dinv prep (count/fill: 4 edges per thread)
    k_zero_cnt<<<(M + 255) / 256, 256>>>(M);
    k_count   <<<(nE / 4 + 255) / 256, 256>>>(ei, nE);
    k_scan    <<<1, 1024>>>(M);
    k_fill    <<<(nE / 4 + 255) / 256, 256>>>(ei, nE);

    dim3 g1(D_HID / 128, (M + 127) / 128);
    dim3 g2(D_OUT / 128, (M + 127) / 128);

    // layer 1: h1 = dinv * (x @ W1) (half), agg1 = relu(dinv*Σ + b1) (half)
    gemm_bf16<D_HID, false><<<g1, 256>>>(x, W1, h1, M);
    k_agg_csr<D_HID, 0><<<(M + 3) / 4, 256>>>(h1, b1, agg1);

    // layer 2: h2 = dinv * (agg1 @ W2) (half), out = sigmoid(dinv*Σ + b2) (fp32)
    gemm_bf16<D_OUT, true><<<g2, 256>>>(agg1, W2, h2, M);
    k_agg_csr<D_OUT, 1><<<(M + 7) / 8, 256>>>(h2, b2, out);
}

// round 17
// speedup vs baseline: 1.0123x; 1.0123x over previous
#include <cuda_runtime.h>
#include <cuda_fp16.h>
#include <cuda_bf16.h>
#include <cstdint>

#define N_NODES 100000
#define N_EDGES 3200000
#define D_IN    256
#define D_HID   256
#define D_OUT   128

// ---------------- scratch (static device globals; no allocation) ----------------
__device__ __half g_h1  [(size_t)N_NODES * D_HID];   // dinv[m] * (X @ W1)   (half, pre-scaled)
__device__ __half g_agg1[(size_t)N_NODES * D_HID];   // relu(agg + b1)       (half)
__device__ __half g_h2  [(size_t)N_NODES * D_OUT];   // dinv[m] * (agg1 @ W2)(half, pre-scaled)
__device__ int    g_esrc[N_EDGES];                   // CSR: src per edge (dst-sorted)
__device__ int    g_rowptr[N_NODES + 1];
__device__ int    g_cursor[N_NODES];
__device__ int    g_cnt   [N_NODES];                 // incoming-edge count (no self loop)
__device__ float  g_dinv  [N_NODES];

// ---------------- prep ----------------
__global__ void k_zero_cnt(int n) {
    int i = blockIdx.x * blockDim.x + threadIdx.x;
    if (i < n) g_cnt[i] = 0;
}

// edge_index is int32 (JAX x64 disabled). 4 edges per thread.
__global__ void k_count(const int* __restrict__ ei, int nE) {
    int t = blockIdx.x * blockDim.x + threadIdx.x;
    if (t * 4 >= nE) return;
    int4 d = ((const int4*)(ei + nE))[t];
    atomicAdd(&g_cnt[d.x], 1);
    atomicAdd(&g_cnt[d.y], 1);
    atomicAdd(&g_cnt[d.z], 1);
    atomicAdd(&g_cnt[d.w], 1);
}

// single-block exclusive scan over g_cnt -> g_rowptr, init g_cursor, compute dinv
__global__ void k_scan(int n) {
    const int T = 1024;
    __shared__ int s[T];
    int t = threadIdx.x;
    int items = (n + T - 1) / T;
    int base = t * items;

    int sum = 0;
    for (int j = 0; j < items; j++) {
        int idx = base + j;
        if (idx < n) sum += g_cnt[idx];
    }
    s[t] = sum;
    __syncthreads();
    for (int off = 1; off < T; off <<= 1) {
        int v = (t >= off) ? s[t - off] : 0;
        __syncthreads();
        s[t] += v;
        __syncthreads();
    }
    int run = s[t] - sum;   // exclusive prefix
    for (int j = 0; j < items; j++) {
        int idx = base + j;
        if (idx < n) {
            int c = g_cnt[idx];
            g_rowptr[idx] = run;
            g_cursor[idx] = run;
            run += c;
            g_dinv[idx] = rsqrtf((float)(c + 1));   // +1 self loop
        }
    }
    if (t == T - 1) g_rowptr[n] = s[T - 1];
}

// 4 edges per thread: int4 src/dst loads, 4 independent cursor atomics,
// 4 independent int scatter stores (src only — norm factorized away).
__global__ void k_fill(const int* __restrict__ ei, int nE) {
    int t = blockIdx.x * blockDim.x + threadIdx.x;
    if (t * 4 >= nE) return;
    int4 s = ((const int4*)ei)[t];
    int4 d = ((const int4*)(ei + nE))[t];
    int p0 = atomicAdd(&g_cursor[d.x], 1);
    int p1 = atomicAdd(&g_cursor[d.y], 1);
    int p2 = atomicAdd(&g_cursor[d.z], 1);
    int p3 = atomicAdd(&g_cursor[d.w], 1);
    g_esrc[p0] = s.x;
    g_esrc[p1] = s.y;
    g_esrc[p2] = s.z;
    g_esrc[p3] = s.w;
}

// ---------------- BF16 tensor-core GEMM: H(half) = dinv[m] * (A @ W) --------
__device__ __forceinline__ uint32_t pack_bf2(float a, float b) {
    __nv_bfloat162 v = __floats2bfloat162_rn(a, b);
    return *(uint32_t*)&v;
}

template<int N, bool A_HALF>
__global__ __launch_bounds__(256, 2)
void gemm_bf16(const void* __restrict__ Av, const float* __restrict__ W,
               __half* __restrict__ H, int M)
{
    constexpr int K  = 256;
    constexpr int BK = 16;
    constexpr int NI = K / BK;                 // 16 slabs
    constexpr int ST = 136;                    // word stride (136 % 32 == 8)
    __shared__ uint32_t As[2][(BK / 2) * ST];
    __shared__ uint32_t Bs[2][(BK / 2) * ST];

    const int tid   = threadIdx.x;
    const int lane  = tid & 31;
    const int wid   = tid >> 5;
    const int warpM = wid & 1;
    const int warpN = wid >> 1;
    const int g     = lane >> 2;
    const int tig   = lane & 3;

    const int bm = blockIdx.y * 128;
    const int bn = blockIdx.x * 128;

    const int arow0 = tid >> 2;                // 0..63
    const int akq0  = (tid & 3) * 4;
    const int arow1 = (tid + 256) >> 2;        // 64..127
    const int hrow  = tid >> 1;                // 0..127
    const int hkq   = (tid & 1) * 8;           // 0 or 8

    float aReg[8];
    uint4 aRaw;
    float bReg[8];

    auto load_tile = [&](int k0) {
        if (A_HALF) {
            const __half* Ah = (const __half*)Av;
            aRaw = make_uint4(0, 0, 0, 0);
            if (bm + hrow < M)
                aRaw = *(const uint4*)(Ah + (size_t)(bm + hrow) * K + k0 + hkq);
        } else {
            const float* A = (const float*)Av;
            float4 a0 = make_float4(0.f, 0.f, 0.f, 0.f);
            float4 a1 = make_float4(0.f, 0.f, 0.f, 0.f);
            if (bm + arow0 < M) a0 = *(const float4*)(A + (size_t)(bm + arow0) * K + k0 + akq0);
            if (bm + arow1 < M) a1 = *(const float4*)(A + (size_t)(bm + arow1) * K + k0 + akq0);
            aReg[0] = a0.x; aReg[1] = a0.y; aReg[2] = a0.z; aReg[3] = a0.w;
            aReg[4] = a1.x; aReg[5] = a1.y; aReg[6] = a1.z; aReg[7] = a1.w;
        }
        #pragma unroll
        for (int it = 0; it < 4; it++) {
            int idx = tid + it * 256;
            int k2  = idx >> 7;
            int n   = idx & 127;
            bReg[it * 2]     = W[(size_t)(k0 + 2 * k2)     * N + bn + n];
            bReg[it * 2 + 1] = W[(size_t)(k0 + 2 * k2 + 1) * N + bn + n];
        }
    };
    auto store_tile = [&](int buf) {
        if (A_HALF) {
            const __half2* hp = (const __half2*)&aRaw;
            #pragma unroll
            for (int j = 0; j < 4; j++) {
                float2 f = __half22float2(hp[j]);
                As[buf][(hkq / 2 + j) * ST + hrow] = pack_bf2(f.x, f.y);
            }
        } else {
            As[buf][(akq0 / 2)     * ST + arow0] = pack_bf2(aReg[0], aReg[1]);
            As[buf][(akq0 / 2 + 1) * ST + arow0] = pack_bf2(aReg[2], aReg[3]);
            As[buf][(akq0 / 2)     * ST + arow1] = pack_bf2(aReg[4], aReg[5]);
            As[buf][(akq0 / 2 + 1) * ST + arow1] = pack_bf2(aReg[6], aReg[7]);
        }
        #pragma unroll
        for (int it = 0; it < 4; it++) {
            int idx = tid + it * 256;
            int k2  = idx >> 7;
            int n   = idx & 127;
            Bs[buf][k2 * ST + n] = pack_bf2(bReg[it * 2], bReg[it * 2 + 1]);
        }
    };

    float c[4][4][4];
    #pragma unroll
    for (int am = 0; am < 4; am++)
        #pragma unroll
        for (int an = 0; an < 4; an++)
            #pragma unroll
            for (int r = 0; r < 4; r++) c[am][an][r] = 0.f;

    load_tile(0);
    store_tile(0);
    __syncthreads();

    for (int it = 0; it < NI; it++) {
        int cur = it & 1;
        if (it + 1 < NI) load_tile((it + 1) * BK);

        uint32_t af[4][4];
        #pragma unroll
        for (int am = 0; am < 4; am++) {
            int m0 = warpM * 64 + am * 16 + g;
            af[am][0] = As[cur][tig       * ST + m0];
            af[am][1] = As[cur][tig       * ST + m0 + 8];
            af[am][2] = As[cur][(tig + 4) * ST + m0];
            af[am][3] = As[cur][(tig + 4) * ST + m0 + 8];
        }
        uint32_t bf[4][2];
        #pragma unroll
        for (int an = 0; an < 4; an++) {
            int n0 = warpN * 32 + an * 8 + g;
            bf[an][0] = Bs[cur][tig       * ST + n0];
            bf[an][1] = Bs[cur][(tig + 4) * ST + n0];
        }
        #pragma unroll
        for (int am = 0; am < 4; am++)
            #pragma unroll
            for (int an = 0; an < 4; an++) {
                asm volatile(
                    "mma.sync.aligned.m16n8k16.row.col.f32.bf16.bf16.f32 "
                    "{%0,%1,%2,%3}, {%4,%5,%6,%7}, {%8,%9}, {%0,%1,%2,%3};"
                    : "+f"(c[am][an][0]), "+f"(c[am][an][1]),
                      "+f"(c[am][an][2]), "+f"(c[am][an][3])
                    : "r"(af[am][0]), "r"(af[am][1]), "r"(af[am][2]), "r"(af[am][3]),
                      "r"(bf[an][0]), "r"(bf[an][1]));
            }

        if (it + 1 < NI) {
            store_tile(1 - cur);
            __syncthreads();
        }
    }

    // ---- epilogue: pre-scale rows by dinv, store half2 pairs ----
    #pragma unroll
    for (int am = 0; am < 4; am++) {
        int row = bm + warpM * 64 + am * 16 + g;
        float d0 = (row     < M) ? g_dinv[row]     : 0.f;
        float d1 = (row + 8 < M) ? g_dinv[row + 8] : 0.f;
        #pragma unroll
        for (int an = 0; an < 4; an++) {
            int col = bn + warpN * 32 + an * 8 + tig * 2;
            if (row < M)
                *(__half2*)(H + (size_t)row * N + col) =
                    __floats2half2_rn(c[am][an][0] * d0, c[am][an][1] * d0);
            if (row + 8 < M)
                *(__half2*)(H + (size_t)(row + 8) * N + col) =
                    __floats2half2_rn(c[am][an][2] * d1, c[am][an][3] * d1);
        }
    }
}

// ---------------- CSR aggregation: unweighted sum of pre-scaled rows ----------
// R15 loop structure (scalar index loads, 8-deep unroll).
__device__ __forceinline__ void unpack4(uint2 r, float* f) {
    float2 a = __half22float2(*(const __half2*)&r.x);
    float2 b = __half22float2(*(const __half2*)&r.y);
    f[0] = a.x; f[1] = a.y; f[2] = b.x; f[3] = b.y;
}

template<int D, int ACT>
__global__ __launch_bounds__(256)
void k_agg_csr(const __half* __restrict__ h, const float* __restrict__ bias,
               void* __restrict__ outp)
{
    constexpr int L   = D / 4;      // lanes per node (64 or 32)
    constexpr int NPB = 256 / L;    // nodes per block (4 or 8)

    int grp  = threadIdx.x / L;
    int lane = threadIdx.x % L;
    int i = blockIdx.x * NPB + grp;
    if (i >= N_NODES) return;

    const uint2* hv = (const uint2*)h;      // row = L uint2s (4 halves each)
    int beg = g_rowptr[i];
    int end = g_rowptr[i + 1];

    float acc[4];
    {
        float f[4]; unpack4(__ldg(hv + (size_t)i * L + lane), f);
        #pragma unroll
        for (int j = 0; j < 4; j++) acc[j] = f[j];   // self loop (pre-scaled)
    }

    int e = beg;
    for (; e + 8 <= end; e += 8) {
        int sidx[8];
        #pragma unroll
        for (int u = 0; u < 8; u++) sidx[u] = __ldg(g_esrc + e + u);
        uint2 r[8];
        #pragma unroll
        for (int u = 0; u < 8; u++)
            r[u] = __ldg(hv + (size_t)sidx[u] * L + lane);
        #pragma unroll
        for (int u = 0; u < 8; u++) {
            float f[4]; unpack4(r[u], f);
            #pragma unroll
            for (int j = 0; j < 4; j++) acc[j] += f[j];
        }
    }
    for (; e < end; e++) {
        float f[4]; unpack4(__ldg(hv + (size_t)__ldg(g_esrc + e) * L + lane), f);
        #pragma unroll
        for (int j = 0; j < 4; j++) acc[j] += f[j];
    }

    float dv = g_dinv[i];
    float4 b = __ldg((const float4*)bias + lane);
    acc[0] = acc[0] * dv + b.x;
    acc[1] = acc[1] * dv + b.y;
    acc[2] = acc[2] * dv + b.z;
    acc[3] = acc[3] * dv + b.w;
    if (ACT == 0) {
        #pragma unroll
        for (int j = 0; j < 4; j++) acc[j] = fmaxf(acc[j], 0.f);
        uint2 r;
        *(__half2*)&r.x = __floats2half2_rn(acc[0], acc[1]);
        *(__half2*)&r.y = __floats2half2_rn(acc[2], acc[3]);
        __stcs((uint2*)outp + (size_t)i * L + lane, r);
    } else {
        #pragma unroll
        for (int j = 0; j < 4; j++) acc[j] = 1.f / (1.f + __expf(-acc[j]));
        __stcs((float4*)((float*)outp + (size_t)i * D + lane * 4),
               make_float4(acc[0], acc[1], acc[2], acc[3]));
    }
}

// ---------------- launch ----------------
extern "C" void kernel_launch(void* const* d_in, const int* in_sizes, int n_in,
                              void* d_out, int out_size)
{
    const float* x  = (const float*)d_in[0];
    const int*   ei = (const int*)d_in[1];      // int32 edge_index [2, E]
    const float* W1 = (const float*)d_in[2];
    const float* b1 = (const float*)d_in[3];
    const float* W2 = (const float*)d_in[4];
    const float* b2 = (const float*)d_in[5];
    float*       out = (float*)d_out;

    const int M  = N_NODES;
    const int nE = N_EDGES;

    __half *h1, *h2, *agg1;
    cudaGetSymbolAddress((void**)&h1,   g_h1);
    cudaGetSymbolAddress((void**)&agg1, g_agg1);
    cudaGetSymbolAddress((void**)&h2,   g_h2);

    // CSR + dinv prep (count/fill: 4 edges per thread)
    k_zero_cnt<<<(M + 255) / 256, 256>>>(M);
    k_count   <<<(nE / 4 + 255) / 256, 256>>>(ei, nE);
    k_scan    <<<1, 1024>>>(M);
    k_fill    <<<(nE / 4 + 255) / 256, 256>>>(ei, nE);

    dim3 g1(D_HID / 128, (M + 127) / 128);
    dim3 g2(D_OUT / 128, (M + 127) / 128);

    // layer 1: h1 = dinv * (x @ W1) (half), agg1 = relu(dinv*Σ + b1) (half)
    gemm_bf16<D_HID, false><<<g1, 256>>>(x, W1, h1, M);
    k_agg_csr<D_HID, 0><<<(M + 3) / 4, 256>>>(h1, b1, agg1);

    // layer 2: h2 = dinv * (agg1 @ W2) (half), out = sigmoid(dinv*Σ + b2) (fp32)
    gemm_bf16<D_OUT, true><<<g2, 256>>>(agg1, W2, h2, M);
    k_agg_csr<D_OUT, 1><<<(M + 7) / 8, 256>>>(h2, b2, out);
}